// round 2
// baseline (speedup 1.0000x reference)
#include <cuda_runtime.h>

#define T_STEPS 1024
#define HID     64
#define NG      256   // 4*HID gate columns
#define NTH     288   // 256 gate threads + 1 layer-2 warp

__device__ __forceinline__ float sigm(float x) {
    return 1.0f / (1.0f + __expf(-x));
}
__device__ __forceinline__ float tanh_f(float x) {
    float ax = fabsf(x);
    float e  = __expf(-2.0f * ax);        // e in (0,1], no overflow
    float t  = (1.0f - e) / (1.0f + e);
    return copysignf(t, x);
}

// One layer-2 LSTM step (hidden size 1), executed by warp 8 (32 lanes).
// ha/hb: this lane's two h1 values. All lanes end with identical c2/h2.
__device__ __forceinline__ void layer2_step(
    float ha, float hb,
    const float* w2a, const float* w2b, const float* w2h, const float* bb2,
    float& c2, float& h2)
{
    float g0 = fmaf(ha, w2a[0], hb * w2b[0]);
    float g1 = fmaf(ha, w2a[1], hb * w2b[1]);
    float g2 = fmaf(ha, w2a[2], hb * w2b[2]);
    float g3 = fmaf(ha, w2a[3], hb * w2b[3]);
    #pragma unroll
    for (int m = 16; m >= 1; m >>= 1) {
        g0 += __shfl_xor_sync(0xffffffffu, g0, m);
        g1 += __shfl_xor_sync(0xffffffffu, g1, m);
        g2 += __shfl_xor_sync(0xffffffffu, g2, m);
        g3 += __shfl_xor_sync(0xffffffffu, g3, m);
    }
    g0 += bb2[0] + h2 * w2h[0];   // i
    g1 += bb2[1] + h2 * w2h[1];   // j
    g2 += bb2[2] + h2 * w2h[2];   // f
    g3 += bb2[3] + h2 * w2h[3];   // o
    c2 = c2 * sigm(g2 + 1.0f) + sigm(g0) * tanh_f(g1);
    h2 = tanh_f(c2) * sigm(g3);
}

__global__ __launch_bounds__(NTH, 2)
void lstm2_kernel(const float* __restrict__ x,
                  const float* __restrict__ W1,
                  const float* __restrict__ b1,
                  const float* __restrict__ W2,
                  const float* __restrict__ b2,
                  float* __restrict__ out)
{
    __shared__ __align__(16) float sx[T_STEPS];
    __shared__ __align__(16) float sh[2][HID];   // double-buffered h1
    __shared__ __align__(16) float sg[NG];       // gate pre-activations

    const int tid = threadIdx.x;
    const int b   = blockIdx.x;

    // Preload this batch's x sequence (contiguous 4 KB) into smem.
    for (int i = tid; i < T_STEPS; i += NTH)
        sx[i] = x[(size_t)b * T_STEPS + i];
    if (tid < HID) { sh[0][tid] = 0.0f; sh[1][tid] = 0.0f; }

    // ---- gate-thread state: one W1 column in registers ----
    float w[65];
    float bg = 0.0f;
    if (tid < NG) {
        #pragma unroll
        for (int k = 0; k < 65; k++) w[k] = W1[k * NG + tid];
        bg = b1[tid];
    }
    float c1 = 0.0f;  // owned by tid < 64

    // ---- layer-2 warp state (threads 256..287) ----
    float w2a[4], w2b[4], w2h[4], bb2[4];
    float c2 = 0.0f, h2 = 0.0f;
    if (tid >= NG) {
        int l = tid - NG;
        #pragma unroll
        for (int g = 0; g < 4; g++) {
            w2a[g] = W2[l * 4 + g];
            w2b[g] = W2[(l + 32) * 4 + g];
            w2h[g] = W2[64 * 4 + g];
            bb2[g] = b2[g];
        }
    }
    __syncthreads();

    float* outb = out + (size_t)b * T_STEPS;
    int cur = 0;  // sh[cur] holds h1(t-1) at loop top

    for (int t = 0; t < T_STEPS; t++) {
        if (tid < NG) {
            // gates(t) = [x_t, h1(t-1)] @ W1 + b1, this thread's column
            float xt   = sx[t];
            float acc0 = fmaf(xt, w[0], bg);
            float acc1 = 0.0f;
            const float4* hv4 = (const float4*)sh[cur];
            #pragma unroll
            for (int kk = 0; kk < 16; kk++) {
                float4 hv = hv4[kk];                     // broadcast LDS.128
                acc0 = fmaf(hv.x, w[4 * kk + 1], acc0);
                acc1 = fmaf(hv.y, w[4 * kk + 2], acc1);
                acc0 = fmaf(hv.z, w[4 * kk + 3], acc0);
                acc1 = fmaf(hv.w, w[4 * kk + 4], acc1);
            }
            sg[tid] = acc0 + acc1;
        } else if (t > 0) {
            // layer 2 for step t-1, overlapped with the gate matvec.
            // sh[cur] = h1(t-1), exactly what this lagging step needs.
            int l = tid - NG;
            float ha = sh[cur][l];
            float hb = sh[cur][l + 32];
            layer2_step(ha, hb, w2a, w2b, w2h, bb2, c2, h2);
            if (l == 0) outb[t - 1] = h2;
        }
        __syncthreads();   // gates ready; warp8 done reading sh[cur]

        if (tid < HID) {
            float gi = sg[tid];
            float gj = sg[HID + tid];
            float gf = sg[2 * HID + tid];
            float go = sg[3 * HID + tid];
            c1 = c1 * sigm(gf + 1.0f) + sigm(gi) * tanh_f(gj);
            sh[cur ^ 1][tid] = tanh_f(c1) * sigm(go);
        }
        __syncthreads();   // h1(t) ready in sh[cur^1]
        cur ^= 1;
    }

    // final layer-2 step for t = T-1 (sh[cur] = h1(T-1))
    if (tid >= NG) {
        int l = tid - NG;
        float ha = sh[cur][l];
        float hb = sh[cur][l + 32];
        layer2_step(ha, hb, w2a, w2b, w2h, bb2, c2, h2);
        if (l == 0) outb[T_STEPS - 1] = h2;
    }
}

extern "C" void kernel_launch(void* const* d_in, const int* in_sizes, int n_in,
                              void* d_out, int out_size)
{
    const float* x  = (const float*)d_in[0];   // [512,1024,1]
    const float* W1 = (const float*)d_in[1];   // [65,256]
    const float* b1 = (const float*)d_in[2];   // [256]
    const float* W2 = (const float*)d_in[3];   // [65,4]
    const float* b2 = (const float*)d_in[4];   // [4]
    float* out = (float*)d_out;                // [512,1024,1]

    (void)in_sizes; (void)n_in; (void)out_size;
    lstm2_kernel<<<512, NTH>>>(x, W1, b1, W2, b2, out);
}

// round 3
// speedup vs baseline: 2.3500x; 2.3500x over previous
#include <cuda_runtime.h>

#define T_STEPS 1024
#define HID     64
#define NG      256           // 4*HID gate columns
#define NB      4             // batches per block (2 packed pairs)
#define NTH     320           // 256 gate/elementwise threads + 2 layer-2 warps

typedef unsigned long long u64;

// packed f32x2 ops (sm_103a; only reachable via PTX)
#define FMA2(d, a, b) asm("fma.rn.f32x2 %0, %1, %2, %0;" : "+l"(d) : "l"(a), "l"(b))
#define ADD2(d, a, b) asm("add.rn.f32x2 %0, %1, %2;"     : "=l"(d) : "l"(a), "l"(b))

__device__ __forceinline__ u64 pack2(float lo, float hi) {
    u64 r;
    asm("mov.b64 %0, {%1, %2};" : "=l"(r) : "f"(lo), "f"(hi));
    return r;
}

__device__ __forceinline__ float sigm(float x) {
    return __fdividef(1.0f, 1.0f + __expf(-x));
}
__device__ __forceinline__ float tanh_f(float x) {
    float e = __expf(-2.0f * fabsf(x));            // e in (0,1], no overflow
    return copysignf(__fdividef(1.0f - e, 1.0f + e), x);
}

__global__ __launch_bounds__(NTH, 1)
void lstm2_kernel(const float* __restrict__ x,
                  const float* __restrict__ W1,
                  const float* __restrict__ b1,
                  const float* __restrict__ W2,
                  const float* __restrict__ b2,
                  float* __restrict__ out)
{
    // x, batch-pair interleaved: sxp[pair][t] = {x_b(2p), x_b(2p+1)}
    __shared__ __align__(16) u64 sxp[2][T_STEPS];
    // h1 double-buffered, pair-interleaved: float view [2*n + half]
    __shared__ __align__(16) u64 shp[2][2][HID];
    // gate pre-activations, packed per pair
    __shared__ __align__(16) u64 sgp[2][NG];

    const int tid  = threadIdx.x;
    const int base = blockIdx.x * NB;          // first batch of this block

    // ---- preload x for 4 batches, packed by pair ----
    for (int i = tid; i < 2 * T_STEPS; i += NTH) {
        int p = i >> 10, t = i & (T_STEPS - 1);
        sxp[p][t] = pack2(x[(size_t)(base + 2 * p)     * T_STEPS + t],
                          x[(size_t)(base + 2 * p + 1) * T_STEPS + t]);
    }
    if (tid < 2 * HID) {                        // zero both h1 buffers
        shp[0][tid >> 6][tid & 63] = 0ULL;
        shp[1][tid >> 6][tid & 63] = 0ULL;
    }

    // ---- gate-thread state: one W1 column, duplicated into f32x2 regs ----
    u64 wp[65];
    u64 bgp = 0ULL;
    if (tid < NG) {
        #pragma unroll
        for (int k = 0; k < 65; k++) {
            float w = W1[k * NG + tid];
            wp[k] = pack2(w, w);
        }
        float bg = b1[tid];
        bgp = pack2(bg, bg);
    }
    // elementwise ownership: (n, b) = (tid&63, tid>>6)
    const int en = tid & 63, eb = tid >> 6, ep = eb >> 1, eh = eb & 1;
    float c1 = 0.0f;

    // ---- layer-2 warps (tid 256..319): warp handles one batch-pair ----
    const int wid  = tid >> 5;
    const int lane = tid & 31;
    const int l2p  = wid - 8;                   // pair id for layer-2 warp
    float w2x[4], w2y[4], w2h[4], bb2[4];
    float c2a = 0.0f, h2a = 0.0f, c2b = 0.0f, h2b = 0.0f;
    if (wid >= 8) {
        #pragma unroll
        for (int g = 0; g < 4; g++) {
            w2x[g] = W2[(2 * lane)     * 4 + g];   // h1 row 2*lane
            w2y[g] = W2[(2 * lane + 1) * 4 + g];   // h1 row 2*lane+1
            w2h[g] = W2[64 * 4 + g];               // h2 recurrent row
            bb2[g] = b2[g];
        }
    }
    __syncthreads();

    float* outb = out + (size_t)base * T_STEPS;
    int cur = 0;                                // shp[cur] = h1(t-1) at loop top

    for (int t = 0; t < T_STEPS; t++) {
        if (tid < NG) {
            // ---- gates(t) for this column, both batch-pairs, packed ----
            u64 aA0 = bgp, aA1 = 0ULL, aB0 = bgp, aB1 = 0ULL;
            FMA2(aA0, sxp[0][t], wp[0]);
            FMA2(aB0, sxp[1][t], wp[0]);
            const ulonglong2* hA = (const ulonglong2*)shp[cur][0];
            const ulonglong2* hB = (const ulonglong2*)shp[cur][1];
            #pragma unroll
            for (int k = 0; k < 32; k++) {
                ulonglong2 v = hA[k];               // broadcast LDS.128
                FMA2(aA0, v.x, wp[2 * k + 1]);
                FMA2(aA1, v.y, wp[2 * k + 2]);
            }
            #pragma unroll
            for (int k = 0; k < 32; k++) {
                ulonglong2 v = hB[k];
                FMA2(aB0, v.x, wp[2 * k + 1]);
                FMA2(aB1, v.y, wp[2 * k + 2]);
            }
            u64 rA, rB;
            ADD2(rA, aA0, aA1);
            ADD2(rB, aB0, aB1);
            sgp[0][tid] = rA;
            sgp[1][tid] = rB;
        } else if (t > 0) {
            // ---- layer 2 for step t-1 (overlapped; reads h1(t-1)) ----
            float4 hv = ((const float4*)shp[cur][l2p])[lane];
            // hv = {h_b0[2l], h_b1[2l], h_b0[2l+1], h_b1[2l+1]}
            float ga[4], gb[4];
            #pragma unroll
            for (int g = 0; g < 4; g++) {
                ga[g] = fmaf(hv.x, w2x[g], hv.z * w2y[g]);   // batch even
                gb[g] = fmaf(hv.y, w2x[g], hv.w * w2y[g]);   // batch odd
            }
            #pragma unroll
            for (int m = 16; m >= 1; m >>= 1) {
                #pragma unroll
                for (int g = 0; g < 4; g++) {
                    ga[g] += __shfl_xor_sync(0xffffffffu, ga[g], m);
                    gb[g] += __shfl_xor_sync(0xffffffffu, gb[g], m);
                }
            }
            #pragma unroll
            for (int g = 0; g < 4; g++) {
                ga[g] += bb2[g] + h2a * w2h[g];
                gb[g] += bb2[g] + h2b * w2h[g];
            }
            c2a = c2a * sigm(ga[2] + 1.0f) + sigm(ga[0]) * tanh_f(ga[1]);
            h2a = tanh_f(c2a) * sigm(ga[3]);
            c2b = c2b * sigm(gb[2] + 1.0f) + sigm(gb[0]) * tanh_f(gb[1]);
            h2b = tanh_f(c2b) * sigm(gb[3]);
            if (lane == 0) {
                outb[(size_t)(2 * l2p)     * T_STEPS + (t - 1)] = h2a;
                outb[(size_t)(2 * l2p + 1) * T_STEPS + (t - 1)] = h2b;
            }
        }
        __syncthreads();   // gates ready; layer-2 done reading shp[cur]

        if (tid < NG) {
            // ---- elementwise: one (n, batch) per thread ----
            const float* sgf = (const float*)sgp[ep];
            float gi = sgf[2 * en + eh];
            float gj = sgf[2 * (HID     + en) + eh];
            float gf = sgf[2 * (2 * HID + en) + eh];
            float go = sgf[2 * (3 * HID + en) + eh];
            c1 = c1 * sigm(gf + 1.0f) + sigm(gi) * tanh_f(gj);
            ((float*)shp[cur ^ 1][ep])[2 * en + eh] = tanh_f(c1) * sigm(go);
        }
        __syncthreads();   // h1(t) ready
        cur ^= 1;
    }

    // ---- final layer-2 step for t = T-1 (shp[cur] = h1(T-1)) ----
    if (wid >= 8) {
        float4 hv = ((const float4*)shp[cur][l2p])[lane];
        float ga[4], gb[4];
        #pragma unroll
        for (int g = 0; g < 4; g++) {
            ga[g] = fmaf(hv.x, w2x[g], hv.z * w2y[g]);
            gb[g] = fmaf(hv.y, w2x[g], hv.w * w2y[g]);
        }
        #pragma unroll
        for (int m = 16; m >= 1; m >>= 1) {
            #pragma unroll
            for (int g = 0; g < 4; g++) {
                ga[g] += __shfl_xor_sync(0xffffffffu, ga[g], m);
                gb[g] += __shfl_xor_sync(0xffffffffu, gb[g], m);
            }
        }
        #pragma unroll
        for (int g = 0; g < 4; g++) {
            ga[g] += bb2[g] + h2a * w2h[g];
            gb[g] += bb2[g] + h2b * w2h[g];
        }
        c2a = c2a * sigm(ga[2] + 1.0f) + sigm(ga[0]) * tanh_f(ga[1]);
        h2a = tanh_f(c2a) * sigm(ga[3]);
        c2b = c2b * sigm(gb[2] + 1.0f) + sigm(gb[0]) * tanh_f(gb[1]);
        h2b = tanh_f(c2b) * sigm(gb[3]);
        if (lane == 0) {
            outb[(size_t)(2 * l2p)     * T_STEPS + (T_STEPS - 1)] = h2a;
            outb[(size_t)(2 * l2p + 1) * T_STEPS + (T_STEPS - 1)] = h2b;
        }
    }
}

extern "C" void kernel_launch(void* const* d_in, const int* in_sizes, int n_in,
                              void* d_out, int out_size)
{
    const float* x  = (const float*)d_in[0];   // [512,1024,1]
    const float* W1 = (const float*)d_in[1];   // [65,256]
    const float* b1 = (const float*)d_in[2];   // [256]
    const float* W2 = (const float*)d_in[3];   // [65,4]
    const float* b2 = (const float*)d_in[4];   // [4]
    float* out = (float*)d_out;                // [512,1024,1]

    (void)in_sizes; (void)n_in; (void)out_size;
    lstm2_kernel<<<512 / NB, NTH>>>(x, W1, b1, W2, b2, out);
}